// round 14
// baseline (speedup 1.0000x reference)
#include <cuda_runtime.h>
#include <cstdint>

// Problem constants (fixed by the dataset)
#define NJ     25
#define CIN    256
#define HID    128
#define BATCH  256

// ---- fused kernel smem layout (float/uint units) ----
#define APITCH 132               // A tile pitch (uint = bf16x2); 528B, 16B-aligned
#define WPITCH 36                // W chunk pitch (uint); 144B, 16B-aligned
#define WPART  4608              // 128 x 36 per part
#define YPAD   132               // y pitch (float)
#define SAH    0                 // A hi tile: 32 x 132 (rows 25-31 garbage)
#define SAL    4224
#define SW     8448              // W bufs: [2 buf][2 part][128 x 36]
#define SYF    8448              // y overlays W buf0 after GEMM
#define SOUTF  17664             // out staging overlays W buf1 (650 floats)
#define SW2O   26880
#define SZO    27008
#define SMEM_FLOATS 27040
#define SMEM_BYTES  (SMEM_FLOATS * 4)    // 108160 -> occ 2

typedef unsigned long long ull;

__device__ unsigned Wh[HID * CIN / 2];     // bf16x2 hi of W1
__device__ unsigned Wl[HID * CIN / 2];

__device__ __forceinline__ void fma2(ull& d, ull a, ull b) {
    asm("fma.rn.f32x2 %0, %1, %2, %0;" : "+l"(d) : "l"(a), "l"(b));
}
__device__ __forceinline__ float lo2(ull v){ return __uint_as_float((unsigned)v); }
__device__ __forceinline__ float hi2(ull v){ return __uint_as_float((unsigned)(v >> 32)); }
__device__ __forceinline__ void cpasync16(uint32_t dst, const void* src) {
    asm volatile("cp.async.cg.shared.global [%0], [%1], 16;\n" :: "r"(dst), "l"(src));
}
__device__ __forceinline__ unsigned pk_bf16x2(float even, float odd) {
    unsigned r;
    asm("cvt.rn.bf16x2.f32 %0, %1, %2;" : "=r"(r) : "f"(odd), "f"(even));
    return r;
}
__device__ __forceinline__ void mma16816(float* d,
    unsigned a0, unsigned a1, unsigned a2, unsigned a3,
    unsigned b0, unsigned b1)
{
    asm volatile(
        "mma.sync.aligned.m16n8k16.row.col.f32.bf16.bf16.f32 "
        "{%0,%1,%2,%3},{%4,%5,%6,%7},{%8,%9},{%0,%1,%2,%3};"
        : "+f"(d[0]), "+f"(d[1]), "+f"(d[2]), "+f"(d[3])
        : "r"(a0), "r"(a1), "r"(a2), "r"(a3), "r"(b0), "r"(b1));
}
__device__ __forceinline__ void ldsm4(unsigned& r0, unsigned& r1,
                                      unsigned& r2, unsigned& r3, uint32_t addr)
{
    asm volatile("ldmatrix.sync.aligned.m8n8.x4.shared.b16 {%0,%1,%2,%3}, [%4];"
                 : "=r"(r0), "=r"(r1), "=r"(r2), "=r"(r3) : "r"(addr));
}

// ============================================================================
// K0: split W1 into bf16 hi/lo
// ============================================================================
#define NW4 (HID * CIN / 4)      // 8192 float4
__global__ __launch_bounds__(256)
void convert_w_kernel(const float* __restrict__ W1)
{
    const int idx = blockIdx.x * 256 + threadIdx.x;
    if (idx >= NW4) return;
    const float4 v = reinterpret_cast<const float4*>(W1)[idx];
    const int o = idx * 2;
    const unsigned h0 = pk_bf16x2(v.x, v.y);
    const unsigned h1 = pk_bf16x2(v.z, v.w);
    const float fx = __uint_as_float(h0 << 16);
    const float fy = __uint_as_float(h0 & 0xFFFF0000u);
    const float fz = __uint_as_float(h1 << 16);
    const float fw = __uint_as_float(h1 & 0xFFFF0000u);
    Wh[o] = h0; Wh[o + 1] = h1;
    Wl[o]     = pk_bf16x2(v.x - fx, v.y - fy);
    Wl[o + 1] = pk_bf16x2(v.z - fz, v.w - fw);
}

// ============================================================================
// K1: fused per-batch kernel.
//   GEMM y = S @ W1^T via mma.sync bf16 split (Sh*Wh + Sh*Wl + Sl*Wh),
//   fragments via ldmatrix; then z; then symmetric phase 3 via smem staging.
// ============================================================================
__global__ __launch_bounds__(256, 2)
void fused_edge_kernel(const float* __restrict__ src,
                       const float* __restrict__ alpha_p,
                       const float* __restrict__ W2,
                       float* __restrict__ out)
{
    extern __shared__ float smemf[];
    unsigned* sm32 = reinterpret_cast<unsigned*>(smemf);
    float* sW2 = smemf + SW2O;
    float* sZ  = smemf + SZO;

    const int tid  = threadIdx.x;
    const int b    = blockIdx.x;
    const int lane = tid & 31, warp = tid >> 5;

    const uint32_t smemB = (uint32_t)__cvta_generic_to_shared(smemf);

    // ---- G0/G1: W chunks 0,1 -> bufs 0,1 (both free at start) ----
    #pragma unroll
    for (int buf = 0; buf < 2; buf++) {
        #pragma unroll
        for (int p = 0; p < 2; p++) {
            const unsigned* g = p ? Wl : Wh;
            #pragma unroll
            for (int k = 0; k < 4; k++) {
                const int i = k * 256 + tid;
                const int r = i >> 3, c8 = i & 7;
                cpasync16(smemB + (uint32_t)(SW + buf * 9216 + p * WPART
                                             + r * WPITCH + c8 * 4) * 4,
                          g + (size_t)r * 128 + buf * 32 + c8 * 4);
            }
        }
        asm volatile("cp.async.commit_group;\n");
    }

    // ---- direct LDG -> bf16 hi/lo convert -> A tiles; W2 ----
    {
        const float* srcB = src + (size_t)b * NJ * CIN;
        #pragma unroll
        for (int k = 0; k < 7; k++) {
            const int idx = k * 256 + tid;
            if (idx < 1600) {
                const float4 v = *reinterpret_cast<const float4*>(srcB + idx * 4);
                const int r = idx >> 6, c4 = idx & 63;
                const unsigned h0 = pk_bf16x2(v.x, v.y);
                const unsigned h1 = pk_bf16x2(v.z, v.w);
                const float fx = __uint_as_float(h0 << 16);
                const float fy = __uint_as_float(h0 & 0xFFFF0000u);
                const float fz = __uint_as_float(h1 << 16);
                const float fw = __uint_as_float(h1 & 0xFFFF0000u);
                const int o = r * APITCH + c4 * 2;
                sm32[SAH + o] = h0; sm32[SAH + o + 1] = h1;
                sm32[SAL + o]     = pk_bf16x2(v.x - fx, v.y - fy);
                sm32[SAL + o + 1] = pk_bf16x2(v.z - fz, v.w - fw);
            }
        }
        if (tid < HID) sW2[tid] = W2[tid];
    }

    // ---- phase 2: split GEMM over 4 k-chunks; ldmatrix fragments ----
    float acc[2][2][4];
    #pragma unroll
    for (int mt = 0; mt < 2; mt++)
        #pragma unroll
        for (int nt = 0; nt < 2; nt++)
            #pragma unroll
            for (int e = 0; e < 4; e++) acc[mt][nt][e] = 0.0f;

    // ldmatrix per-thread base addresses (bytes)
    const uint32_t aBaseH = smemB + (uint32_t)(((lane & 15) * APITCH + (lane >> 4) * 4) * 4);
    const uint32_t aBaseL = aBaseH + SAL * 4;
    const int wb = warp * 16;
    const uint32_t bBase  = smemB + (uint32_t)((SW + (wb + (lane & 7) + ((lane >> 4) << 3)) * WPITCH
                                                + (((lane >> 3) & 1) << 2)) * 4);

    #pragma unroll 1
    for (int kc = 0; kc < 4; kc++) {
        asm volatile("cp.async.wait_group %0;\n" :: "n"(1) : "memory");
        if (kc == 3) asm volatile("cp.async.wait_group 0;\n" ::: "memory");
        __syncthreads();           // chunk kc + (kc=0: A tiles) visible

        const uint32_t aOff = (uint32_t)(kc * 128);          // kc*32 uints
        const uint32_t bOff = (uint32_t)((kc & 1) * 9216 * 4);

        #pragma unroll
        for (int ks = 0; ks < 4; ks++) {
            const uint32_t kB = (uint32_t)(ks * 32);
            unsigned aH0,aH1,aH2,aH3, aH4,aH5,aH6,aH7;
            unsigned aL0,aL1,aL2,aL3, aL4,aL5,aL6,aL7;
            unsigned bH0,bH1,bH2,bH3, bL0,bL1,bL2,bL3;
            ldsm4(aH0,aH1,aH2,aH3, aBaseH + aOff + kB);
            ldsm4(aH4,aH5,aH6,aH7, aBaseH + aOff + kB + 16 * APITCH * 4);
            ldsm4(aL0,aL1,aL2,aL3, aBaseL + aOff + kB);
            ldsm4(aL4,aL5,aL6,aL7, aBaseL + aOff + kB + 16 * APITCH * 4);
            ldsm4(bH0,bH1,bH2,bH3, bBase + bOff + kB);
            ldsm4(bL0,bL1,bL2,bL3, bBase + bOff + kB + WPART * 4);

            // Sh*Wh
            mma16816(acc[0][0], aH0, aH1, aH2, aH3, bH0, bH1);
            mma16816(acc[0][1], aH0, aH1, aH2, aH3, bH2, bH3);
            mma16816(acc[1][0], aH4, aH5, aH6, aH7, bH0, bH1);
            mma16816(acc[1][1], aH4, aH5, aH6, aH7, bH2, bH3);
            // Sh*Wl
            mma16816(acc[0][0], aH0, aH1, aH2, aH3, bL0, bL1);
            mma16816(acc[0][1], aH0, aH1, aH2, aH3, bL2, bL3);
            mma16816(acc[1][0], aH4, aH5, aH6, aH7, bL0, bL1);
            mma16816(acc[1][1], aH4, aH5, aH6, aH7, bL2, bL3);
            // Sl*Wh
            mma16816(acc[0][0], aL0, aL1, aL2, aL3, bH0, bH1);
            mma16816(acc[0][1], aL0, aL1, aL2, aL3, bH2, bH3);
            mma16816(acc[1][0], aL4, aL5, aL6, aL7, bH0, bH1);
            mma16816(acc[1][1], aL4, aL5, aL6, aL7, bH2, bH3);
        }

        __syncthreads();           // all reads of buf[kc&1] done
        if (kc + 2 < 4) {          // refill with chunk kc+2
            #pragma unroll
            for (int p = 0; p < 2; p++) {
                const unsigned* g = p ? Wl : Wh;
                #pragma unroll
                for (int k = 0; k < 4; k++) {
                    const int i = k * 256 + tid;
                    const int r = i >> 3, c8 = i & 7;
                    cpasync16(smemB + (uint32_t)(SW + (kc & 1) * 9216 + p * WPART
                                                 + r * WPITCH + c8 * 4) * 4,
                              g + (size_t)r * 128 + (kc + 2) * 32 + c8 * 4);
                }
            }
        }
        asm volatile("cp.async.commit_group;\n");   // may be empty
    }

    // ---- store y into sY (overlays W buf0) ----
    float* sY = smemf + SYF;
    {
        const int ra = lane >> 2, q = lane & 3;
        #pragma unroll
        for (int mt = 0; mt < 2; mt++) {
            #pragma unroll
            for (int nt = 0; nt < 2; nt++) {
                const int col = warp * 16 + nt * 8 + 2 * q;
                const int r0 = mt * 16 + ra;
                if (r0 < NJ)
                    *reinterpret_cast<float2*>(sY + r0 * YPAD + col) =
                        make_float2(acc[mt][nt][0], acc[mt][nt][1]);
                if (r0 + 8 < NJ)
                    *reinterpret_cast<float2*>(sY + (r0 + 8) * YPAD + col) =
                        make_float2(acc[mt][nt][2], acc[mt][nt][3]);
            }
        }
    }
    __syncthreads();

    // ---- z[n] = sum_h W2[h]*y[n][h] (warp per n) ----
    for (int n = warp; n < NJ; n += 8) {
        const float* yr = sY + n * YPAD;
        float v = sW2[lane]      * yr[lane]
                + sW2[lane + 32] * yr[lane + 32]
                + sW2[lane + 64] * yr[lane + 64]
                + sW2[lane + 96] * yr[lane + 96];
        #pragma unroll
        for (int o = 16; o > 0; o >>= 1)
            v += __shfl_xor_sync(0xffffffffu, v, o);
        if (lane == 0) sZ[n] = v;
    }
    float* sOut = smemf + SOUTF;
    if (tid < NJ) sOut[tid * 26 + tid] = 0.0f;   // diagonal
    __syncthreads();

    // ---- phase 3: symmetric pairs i<j (12 x 25-lane iterations) ----
    {
        const float alpha = alpha_p[0];
        const float c1 = 0.5f * (1.0f + alpha);
        const float c2 = 0.5f * (1.0f - alpha);
        const ull NEG1  = 0xBF800000BF800000ull;
        const ull AMASK = 0x7FFFFFFF7FFFFFFFull;

        #pragma unroll 1
        for (int it = warp; it < 12; it += 8) {
            // rows i1=it (len 24-it) and i2=23-it (len it+1): exactly 25 lanes
            const int i2 = 23 - it;
            const int boundary = 24 - it;
            int i, j;
            if (lane < boundary)      { i = it; j = it + 1 + lane; }
            else if (lane < NJ)       { i = i2; j = i2 + 1 + (lane - boundary); }
            else                      { i = 0;  j = 1; }     // dummy

            const float* yir = sY + i * YPAD;
            const float* yjr = sY + j * YPAD;
            ull aP = 0ull, aQ = 0ull;
            #pragma unroll 8
            for (int u = 0; u < 32; u++) {
                const ulonglong2 yi = *reinterpret_cast<const ulonglong2*>(yir + 4 * u);
                const ulonglong2 yj = *reinterpret_cast<const ulonglong2*>(yjr + 4 * u);
                const ulonglong2 w  = *reinterpret_cast<const ulonglong2*>(sW2 + 4 * u);
                ull d;
                d = yj.x; fma2(d, yi.x, NEG1); d &= AMASK; fma2(aP, d, w.x);
                d = yj.y; fma2(d, yi.y, NEG1); d &= AMASK; fma2(aQ, d, w.y);
            }
            if (lane < NJ) {
                const float S  = lo2(aP) + hi2(aP) + lo2(aQ) + hi2(aQ);
                const float zd = sZ[j] - sZ[i];
                sOut[i * 26 + j] =  c1 * zd + c2 * S;
                sOut[j * 26 + i] = -c1 * zd + c2 * S;
            }
        }
    }
    __syncthreads();

    // ---- coalesced copy-out ----
    {
        float* outB = out + (size_t)b * NJ * NJ;
        #pragma unroll
        for (int k = 0; k < 3; k++) {
            const int p = k * 256 + tid;
            if (p < NJ * NJ) {
                const int i = p / NJ;
                outB[p] = sOut[i * 26 + (p - i * NJ)];
            }
        }
    }
}

extern "C" void kernel_launch(void* const* d_in, const int* in_sizes, int n_in,
                              void* d_out, int out_size)
{
    // metadata order: src, heads, ends, pair_ids, W1, alpha, W2
    const float* src   = (const float*)d_in[0];
    const float* W1    = (const float*)d_in[4];
    const float* alpha = (const float*)d_in[5];
    const float* W2    = (const float*)d_in[6];
    float* out = (float*)d_out;

    cudaFuncSetAttribute(fused_edge_kernel,
                         cudaFuncAttributeMaxDynamicSharedMemorySize, SMEM_BYTES);

    const int batch = in_sizes[0] / (NJ * CIN);          // 256
    convert_w_kernel<<<(NW4 + 255) / 256, 256>>>(W1);
    fused_edge_kernel<<<batch, 256, SMEM_BYTES>>>(src, alpha, W2, out);
}

// round 15
// speedup vs baseline: 1.0142x; 1.0142x over previous
#include <cuda_runtime.h>
#include <cstdint>

// Problem constants (fixed by the dataset)
#define NJ     25
#define CIN    256
#define HID    128
#define BATCH  256

// ---- fused kernel smem layout (float/uint units) ----
#define APITCH 132               // A tile pitch (uint = bf16x2); 528B, 16B-aligned
#define WPITCH 36                // W chunk pitch (uint); 144B, 16B-aligned
#define WPART  4608              // 128 x 36 per part
#define YPAD   132               // y pitch (float)
#define SAH    0                 // A hi tile: 32 x 132 (rows 25-31 garbage)
#define SAL    4224
#define SW     8448              // W bufs: [2 buf][2 part][128 x 36]
#define SYF    8448              // y overlays W buf0 after GEMM
#define SW2O   26880
#define SZO    27008
#define SMEM_FLOATS 27040
#define SMEM_BYTES  (SMEM_FLOATS * 4)    // 108160 -> occ 2

typedef unsigned long long ull;

__device__ unsigned Wh[HID * CIN / 2];     // bf16x2 hi of W1
__device__ unsigned Wl[HID * CIN / 2];

__device__ __forceinline__ void fma2(ull& d, ull a, ull b) {
    asm("fma.rn.f32x2 %0, %1, %2, %0;" : "+l"(d) : "l"(a), "l"(b));
}
__device__ __forceinline__ float lo2(ull v){ return __uint_as_float((unsigned)v); }
__device__ __forceinline__ float hi2(ull v){ return __uint_as_float((unsigned)(v >> 32)); }
__device__ __forceinline__ void cpasync16(uint32_t dst, const void* src) {
    asm volatile("cp.async.cg.shared.global [%0], [%1], 16;\n" :: "r"(dst), "l"(src));
}
__device__ __forceinline__ unsigned pk_bf16x2(float even, float odd) {
    unsigned r;
    asm("cvt.rn.bf16x2.f32 %0, %1, %2;" : "=r"(r) : "f"(odd), "f"(even));
    return r;
}
__device__ __forceinline__ void mma16816(float* d,
    unsigned a0, unsigned a1, unsigned a2, unsigned a3,
    unsigned b0, unsigned b1)
{
    asm volatile(
        "mma.sync.aligned.m16n8k16.row.col.f32.bf16.bf16.f32 "
        "{%0,%1,%2,%3},{%4,%5,%6,%7},{%8,%9},{%0,%1,%2,%3};"
        : "+f"(d[0]), "+f"(d[1]), "+f"(d[2]), "+f"(d[3])
        : "r"(a0), "r"(a1), "r"(a2), "r"(a3), "r"(b0), "r"(b1));
}
__device__ __forceinline__ void ldsm4(unsigned& r0, unsigned& r1,
                                      unsigned& r2, unsigned& r3, uint32_t addr)
{
    asm volatile("ldmatrix.sync.aligned.m8n8.x4.shared.b16 {%0,%1,%2,%3}, [%4];"
                 : "=r"(r0), "=r"(r1), "=r"(r2), "=r"(r3) : "r"(addr));
}

// ============================================================================
// K0: split W1 into bf16 hi/lo
// ============================================================================
#define NW4 (HID * CIN / 4)      // 8192 float4
__global__ __launch_bounds__(256)
void convert_w_kernel(const float* __restrict__ W1)
{
    const int idx = blockIdx.x * 256 + threadIdx.x;
    if (idx >= NW4) return;
    const float4 v = reinterpret_cast<const float4*>(W1)[idx];
    const int o = idx * 2;
    const unsigned h0 = pk_bf16x2(v.x, v.y);
    const unsigned h1 = pk_bf16x2(v.z, v.w);
    const float fx = __uint_as_float(h0 << 16);
    const float fy = __uint_as_float(h0 & 0xFFFF0000u);
    const float fz = __uint_as_float(h1 << 16);
    const float fw = __uint_as_float(h1 & 0xFFFF0000u);
    Wh[o] = h0; Wh[o + 1] = h1;
    Wl[o]     = pk_bf16x2(v.x - fx, v.y - fy);
    Wl[o + 1] = pk_bf16x2(v.z - fz, v.w - fw);
}

// ============================================================================
// K1: fused per-batch kernel.
//   GEMM y = S @ W1^T via mma.sync bf16 split (Sh*Wh + Sh*Wl + Sl*Wh),
//   fragments via ldmatrix (R14); z + phase 3 = R13's 8-chain epilogue.
// ============================================================================
__global__ __launch_bounds__(256, 2)
void fused_edge_kernel(const float* __restrict__ src,
                       const float* __restrict__ alpha_p,
                       const float* __restrict__ W2,
                       float* __restrict__ out)
{
    extern __shared__ float smemf[];
    unsigned* sm32 = reinterpret_cast<unsigned*>(smemf);
    float* sW2 = smemf + SW2O;
    float* sZ  = smemf + SZO;

    const int tid  = threadIdx.x;
    const int b    = blockIdx.x;
    const int lane = tid & 31, warp = tid >> 5;

    const uint32_t smemB = (uint32_t)__cvta_generic_to_shared(smemf);

    // ---- G0/G1: W chunks 0,1 -> bufs 0,1 ----
    #pragma unroll
    for (int buf = 0; buf < 2; buf++) {
        #pragma unroll
        for (int p = 0; p < 2; p++) {
            const unsigned* g = p ? Wl : Wh;
            #pragma unroll
            for (int k = 0; k < 4; k++) {
                const int i = k * 256 + tid;
                const int r = i >> 3, c8 = i & 7;
                cpasync16(smemB + (uint32_t)(SW + buf * 9216 + p * WPART
                                             + r * WPITCH + c8 * 4) * 4,
                          g + (size_t)r * 128 + buf * 32 + c8 * 4);
            }
        }
        asm volatile("cp.async.commit_group;\n");
    }

    // ---- direct LDG -> bf16 hi/lo convert -> A tiles; W2 ----
    {
        const float* srcB = src + (size_t)b * NJ * CIN;
        #pragma unroll
        for (int k = 0; k < 7; k++) {
            const int idx = k * 256 + tid;
            if (idx < 1600) {
                const float4 v = *reinterpret_cast<const float4*>(srcB + idx * 4);
                const int r = idx >> 6, c4 = idx & 63;
                const unsigned h0 = pk_bf16x2(v.x, v.y);
                const unsigned h1 = pk_bf16x2(v.z, v.w);
                const float fx = __uint_as_float(h0 << 16);
                const float fy = __uint_as_float(h0 & 0xFFFF0000u);
                const float fz = __uint_as_float(h1 << 16);
                const float fw = __uint_as_float(h1 & 0xFFFF0000u);
                const int o = r * APITCH + c4 * 2;
                sm32[SAH + o] = h0; sm32[SAH + o + 1] = h1;
                sm32[SAL + o]     = pk_bf16x2(v.x - fx, v.y - fy);
                sm32[SAL + o + 1] = pk_bf16x2(v.z - fz, v.w - fw);
            }
        }
        if (tid < HID) sW2[tid] = W2[tid];
    }

    // ---- phase 2: split GEMM over 4 k-chunks; ldmatrix fragments ----
    float acc[2][2][4];
    #pragma unroll
    for (int mt = 0; mt < 2; mt++)
        #pragma unroll
        for (int nt = 0; nt < 2; nt++)
            #pragma unroll
            for (int e = 0; e < 4; e++) acc[mt][nt][e] = 0.0f;

    const uint32_t aBaseH = smemB + (uint32_t)(((lane & 15) * APITCH + (lane >> 4) * 4) * 4);
    const uint32_t aBaseL = aBaseH + SAL * 4;
    const int wb = warp * 16;
    const uint32_t bBase  = smemB + (uint32_t)((SW + (wb + (lane & 7) + ((lane >> 4) << 3)) * WPITCH
                                                + (((lane >> 3) & 1) << 2)) * 4);

    #pragma unroll 1
    for (int kc = 0; kc < 4; kc++) {
        asm volatile("cp.async.wait_group %0;\n" :: "n"(1) : "memory");
        if (kc == 3) asm volatile("cp.async.wait_group 0;\n" ::: "memory");
        __syncthreads();           // chunk kc + (kc=0: A tiles) visible

        const uint32_t aOff = (uint32_t)(kc * 128);          // kc*32 uints
        const uint32_t bOff = (uint32_t)((kc & 1) * 9216 * 4);

        #pragma unroll
        for (int ks = 0; ks < 4; ks++) {
            const uint32_t kB = (uint32_t)(ks * 32);
            unsigned aH0,aH1,aH2,aH3, aH4,aH5,aH6,aH7;
            unsigned aL0,aL1,aL2,aL3, aL4,aL5,aL6,aL7;
            unsigned bH0,bH1,bH2,bH3, bL0,bL1,bL2,bL3;
            ldsm4(aH0,aH1,aH2,aH3, aBaseH + aOff + kB);
            ldsm4(aH4,aH5,aH6,aH7, aBaseH + aOff + kB + 16 * APITCH * 4);
            ldsm4(aL0,aL1,aL2,aL3, aBaseL + aOff + kB);
            ldsm4(aL4,aL5,aL6,aL7, aBaseL + aOff + kB + 16 * APITCH * 4);
            ldsm4(bH0,bH1,bH2,bH3, bBase + bOff + kB);
            ldsm4(bL0,bL1,bL2,bL3, bBase + bOff + kB + WPART * 4);

            // Sh*Wh
            mma16816(acc[0][0], aH0, aH1, aH2, aH3, bH0, bH1);
            mma16816(acc[0][1], aH0, aH1, aH2, aH3, bH2, bH3);
            mma16816(acc[1][0], aH4, aH5, aH6, aH7, bH0, bH1);
            mma16816(acc[1][1], aH4, aH5, aH6, aH7, bH2, bH3);
            // Sh*Wl
            mma16816(acc[0][0], aH0, aH1, aH2, aH3, bL0, bL1);
            mma16816(acc[0][1], aH0, aH1, aH2, aH3, bL2, bL3);
            mma16816(acc[1][0], aH4, aH5, aH6, aH7, bL0, bL1);
            mma16816(acc[1][1], aH4, aH5, aH6, aH7, bL2, bL3);
            // Sl*Wh
            mma16816(acc[0][0], aL0, aL1, aL2, aL3, bH0, bH1);
            mma16816(acc[0][1], aL0, aL1, aL2, aL3, bH2, bH3);
            mma16816(acc[1][0], aL4, aL5, aL6, aL7, bH0, bH1);
            mma16816(acc[1][1], aL4, aL5, aL6, aL7, bH2, bH3);
        }

        __syncthreads();           // all reads of buf[kc&1] done
        if (kc + 2 < 4) {          // refill with chunk kc+2
            #pragma unroll
            for (int p = 0; p < 2; p++) {
                const unsigned* g = p ? Wl : Wh;
                #pragma unroll
                for (int k = 0; k < 4; k++) {
                    const int i = k * 256 + tid;
                    const int r = i >> 3, c8 = i & 7;
                    cpasync16(smemB + (uint32_t)(SW + (kc & 1) * 9216 + p * WPART
                                                 + r * WPITCH + c8 * 4) * 4,
                              g + (size_t)r * 128 + (kc + 2) * 32 + c8 * 4);
                }
            }
        }
        asm volatile("cp.async.commit_group;\n");   // may be empty
    }

    // ---- store y into sY (overlays W buf0) ----
    float* sY = smemf + SYF;
    {
        const int ra = lane >> 2, q = lane & 3;
        #pragma unroll
        for (int mt = 0; mt < 2; mt++) {
            #pragma unroll
            for (int nt = 0; nt < 2; nt++) {
                const int col = warp * 16 + nt * 8 + 2 * q;
                const int r0 = mt * 16 + ra;
                if (r0 < NJ)
                    *reinterpret_cast<float2*>(sY + r0 * YPAD + col) =
                        make_float2(acc[mt][nt][0], acc[mt][nt][1]);
                if (r0 + 8 < NJ)
                    *reinterpret_cast<float2*>(sY + (r0 + 8) * YPAD + col) =
                        make_float2(acc[mt][nt][2], acc[mt][nt][3]);
            }
        }
    }
    __syncthreads();

    // ---- z[n] = sum_h W2[h]*y[n][h] (warp per n) ----
    for (int n = warp; n < NJ; n += 8) {
        const float* yr = sY + n * YPAD;
        float v = sW2[lane]      * yr[lane]
                + sW2[lane + 32] * yr[lane + 32]
                + sW2[lane + 64] * yr[lane + 64]
                + sW2[lane + 96] * yr[lane + 96];
        #pragma unroll
        for (int o = 16; o > 0; o >>= 1)
            v += __shfl_xor_sync(0xffffffffu, v, o);
        if (lane == 0) sZ[n] = v;
    }
    __syncthreads();

    // ---- phase 3 (R13): j on lanes, i = warp + 8t; 8 indep chains/warp ----
    {
        const float alpha = alpha_p[0];
        const float c1 = 0.5f * (1.0f + alpha);
        const float c2 = 0.5f * (1.0f - alpha);
        const ull NEG1  = 0xBF800000BF800000ull;
        const ull AMASK = 0x7FFFFFFF7FFFFFFFull;

        ull accP[4] = {0ull, 0ull, 0ull, 0ull};
        ull accQ[4] = {0ull, 0ull, 0ull, 0ull};
        const int jr = (lane < NJ) ? lane : (NJ - 1);
        const float* yjrow = sY + jr * YPAD;

        #pragma unroll
        for (int hc = 0; hc < 8; hc++) {
            const int hb = hc * 16;
            const ulonglong2 yjA = *reinterpret_cast<const ulonglong2*>(yjrow + hb);
            const ulonglong2 yjB = *reinterpret_cast<const ulonglong2*>(yjrow + hb + 4);
            const ulonglong2 yjC = *reinterpret_cast<const ulonglong2*>(yjrow + hb + 8);
            const ulonglong2 yjD = *reinterpret_cast<const ulonglong2*>(yjrow + hb + 12);
            const ulonglong2 wA  = *reinterpret_cast<const ulonglong2*>(sW2 + hb);
            const ulonglong2 wB  = *reinterpret_cast<const ulonglong2*>(sW2 + hb + 4);
            const ulonglong2 wC  = *reinterpret_cast<const ulonglong2*>(sW2 + hb + 8);
            const ulonglong2 wD  = *reinterpret_cast<const ulonglong2*>(sW2 + hb + 12);

            #pragma unroll
            for (int t = 0; t < 4; t++) {
                const int i = warp + 8 * t;
                if (i < NJ) {
                    const float* yir = sY + i * YPAD + hb;
                    const ulonglong2 yiA = *reinterpret_cast<const ulonglong2*>(yir);
                    const ulonglong2 yiB = *reinterpret_cast<const ulonglong2*>(yir + 4);
                    const ulonglong2 yiC = *reinterpret_cast<const ulonglong2*>(yir + 8);
                    const ulonglong2 yiD = *reinterpret_cast<const ulonglong2*>(yir + 12);
                    ull d;
                    d = yjA.x; fma2(d, yiA.x, NEG1); d &= AMASK; fma2(accP[t], d, wA.x);
                    d = yjA.y; fma2(d, yiA.y, NEG1); d &= AMASK; fma2(accQ[t], d, wA.y);
                    d = yjB.x; fma2(d, yiB.x, NEG1); d &= AMASK; fma2(accP[t], d, wB.x);
                    d = yjB.y; fma2(d, yiB.y, NEG1); d &= AMASK; fma2(accQ[t], d, wB.y);
                    d = yjC.x; fma2(d, yiC.x, NEG1); d &= AMASK; fma2(accP[t], d, wC.x);
                    d = yjC.y; fma2(d, yiC.y, NEG1); d &= AMASK; fma2(accQ[t], d, wC.y);
                    d = yjD.x; fma2(d, yiD.x, NEG1); d &= AMASK; fma2(accP[t], d, wD.x);
                    d = yjD.y; fma2(d, yiD.y, NEG1); d &= AMASK; fma2(accQ[t], d, wD.y);
                }
            }
        }

        float* outB = out + (size_t)b * NJ * NJ;
        if (lane < NJ) {
            const float zj = sZ[lane];
            #pragma unroll
            for (int t = 0; t < 4; t++) {
                const int i = warp + 8 * t;
                if (i < NJ) {
                    const float S = lo2(accP[t]) + hi2(accP[t])
                                  + lo2(accQ[t]) + hi2(accQ[t]);
                    outB[i * NJ + lane] = c1 * (zj - sZ[i]) + c2 * S;
                }
            }
        }
    }
}

extern "C" void kernel_launch(void* const* d_in, const int* in_sizes, int n_in,
                              void* d_out, int out_size)
{
    // metadata order: src, heads, ends, pair_ids, W1, alpha, W2
    const float* src   = (const float*)d_in[0];
    const float* W1    = (const float*)d_in[4];
    const float* alpha = (const float*)d_in[5];
    const float* W2    = (const float*)d_in[6];
    float* out = (float*)d_out;

    cudaFuncSetAttribute(fused_edge_kernel,
                         cudaFuncAttributeMaxDynamicSharedMemorySize, SMEM_BYTES);

    const int batch = in_sizes[0] / (NJ * CIN);          // 256
    convert_w_kernel<<<(NW4 + 255) / 256, 256>>>(W1);
    fused_edge_kernel<<<batch, 256, SMEM_BYTES>>>(src, alpha, W2, out);
}

// round 16
// speedup vs baseline: 1.1224x; 1.1066x over previous
#include <cuda_runtime.h>
#include <cstdint>

// Problem constants (fixed by the dataset)
#define NJ     25
#define CIN    256
#define HID    128

// ---- smem layout (float/uint units) ----
#define APITCH 132               // A tile pitch (uint = bf16x2)
#define WPITCH 36                // W conv-chunk pitch (uint)
#define CPART  4608              // 128 x 36 per part
#define YPAD   132               // y pitch (float)
#define SAH    0                 // A hi tile: 32 x 132 (rows 25-31 garbage)
#define SAL    4224
#define SC     8448              // conv W chunk: [2 parts][128][36] = 9216
#define SF     17664             // fp32 W stage: 128 x 64 floats = 8192
#define SYF    17664             // y overlays F after GEMM
#define SW2O   25856
#define SZO    25984
#define SMEM_FLOATS 26016
#define SMEM_BYTES  (SMEM_FLOATS * 4)    // 104064 B -> occ 2

typedef unsigned long long ull;

__device__ __forceinline__ void fma2(ull& d, ull a, ull b) {
    asm("fma.rn.f32x2 %0, %1, %2, %0;" : "+l"(d) : "l"(a), "l"(b));
}
__device__ __forceinline__ float lo2(ull v){ return __uint_as_float((unsigned)v); }
__device__ __forceinline__ float hi2(ull v){ return __uint_as_float((unsigned)(v >> 32)); }
__device__ __forceinline__ void cpasync16(uint32_t dst, const void* src) {
    asm volatile("cp.async.cg.shared.global [%0], [%1], 16;\n" :: "r"(dst), "l"(src));
}
__device__ __forceinline__ unsigned pk_bf16x2(float even, float odd) {
    unsigned r;
    asm("cvt.rn.bf16x2.f32 %0, %1, %2;" : "=r"(r) : "f"(odd), "f"(even));
    return r;
}
__device__ __forceinline__ void mma16816(float* d,
    unsigned a0, unsigned a1, unsigned a2, unsigned a3,
    unsigned b0, unsigned b1)
{
    asm volatile(
        "mma.sync.aligned.m16n8k16.row.col.f32.bf16.bf16.f32 "
        "{%0,%1,%2,%3},{%4,%5,%6,%7},{%8,%9},{%0,%1,%2,%3};"
        : "+f"(d[0]), "+f"(d[1]), "+f"(d[2]), "+f"(d[3])
        : "r"(a0), "r"(a1), "r"(a2), "r"(a3), "r"(b0), "r"(b1));
}

// ============================================================================
// Single fused per-batch kernel.
//   Stage fp32 W1 chunks (same bytes as pre-split bf16 hi+lo), convert to
//   bf16 hi/lo in-block; GEMM y = S @ W1^T via mma.sync split
//   (Sh*Wh + Sh*Wl + Sl*Wh, fp32 acc, scalar fragment loads = R13-proven);
//   then z-reduction + R13 phase-3 epilogue.
// ============================================================================
__global__ __launch_bounds__(256, 2)
void fused_edge_kernel(const float* __restrict__ src,
                       const float* __restrict__ W1,
                       const float* __restrict__ alpha_p,
                       const float* __restrict__ W2,
                       float* __restrict__ out)
{
    extern __shared__ float smemf[];
    unsigned* sm32 = reinterpret_cast<unsigned*>(smemf);
    float* sW2 = smemf + SW2O;
    float* sZ  = smemf + SZO;

    const int tid  = threadIdx.x;
    const int b    = blockIdx.x;
    const int lane = tid & 31, warp = tid >> 5;

    const uint32_t smemB = (uint32_t)__cvta_generic_to_shared(smemf);

    // ---- prologue: stage fp32 W chunk 0 -> F ----
    #pragma unroll
    for (int k = 0; k < 8; k++) {                 // 2048 float4
        const int idx = k * 256 + tid;
        const int r = idx >> 4, c = idx & 15;
        cpasync16(smemB + (uint32_t)(SF + r * 64 + c * 4) * 4,
                  W1 + (size_t)r * CIN + c * 4);
    }
    asm volatile("cp.async.commit_group;\n");

    // ---- direct LDG -> bf16 hi/lo convert -> A tiles; W2 ----
    {
        const float* srcB = src + (size_t)b * NJ * CIN;
        #pragma unroll
        for (int k = 0; k < 7; k++) {
            const int idx = k * 256 + tid;
            if (idx < 1600) {
                const float4 v = *reinterpret_cast<const float4*>(srcB + idx * 4);
                const int r = idx >> 6, c4 = idx & 63;
                const unsigned h0 = pk_bf16x2(v.x, v.y);
                const unsigned h1 = pk_bf16x2(v.z, v.w);
                const float fx = __uint_as_float(h0 << 16);
                const float fy = __uint_as_float(h0 & 0xFFFF0000u);
                const float fz = __uint_as_float(h1 << 16);
                const float fw = __uint_as_float(h1 & 0xFFFF0000u);
                const int o = r * APITCH + c4 * 2;
                sm32[SAH + o] = h0; sm32[SAH + o + 1] = h1;
                sm32[SAL + o]     = pk_bf16x2(v.x - fx, v.y - fy);
                sm32[SAL + o + 1] = pk_bf16x2(v.z - fz, v.w - fw);
            }
        }
        if (tid < HID) sW2[tid] = W2[tid];
    }

    // ---- phase 2: split GEMM over 4 k-chunks of 64 c ----
    float acc[2][2][4];
    #pragma unroll
    for (int mt = 0; mt < 2; mt++)
        #pragma unroll
        for (int nt = 0; nt < 2; nt++)
            #pragma unroll
            for (int e = 0; e < 4; e++) acc[mt][nt][e] = 0.0f;

    const int ra = lane >> 2;       // fragment row/col group
    const int q  = lane & 3;        // thread-in-group
    const int h0 = warp * 16 + ra;
    const int h1 = h0 + 8;

    #pragma unroll 1
    for (int kc = 0; kc < 4; kc++) {
        asm volatile("cp.async.wait_group 0;\n" ::: "memory");
        __syncthreads();            // F(kc) visible; prior MMA reads of C done

        // ---- convert F (fp32) -> C (bf16 hi/lo, pitch-36 layout) ----
        #pragma unroll
        for (int k = 0; k < 8; k++) {
            const int idx = k * 256 + tid;
            const int r = idx >> 4, c = idx & 15;
            const float4 v = *reinterpret_cast<const float4*>(smemf + SF + idx * 4);
            const unsigned h0v = pk_bf16x2(v.x, v.y);
            const unsigned h1v = pk_bf16x2(v.z, v.w);
            const float fx = __uint_as_float(h0v << 16);
            const float fy = __uint_as_float(h0v & 0xFFFF0000u);
            const float fz = __uint_as_float(h1v << 16);
            const float fw = __uint_as_float(h1v & 0xFFFF0000u);
            const int o = r * WPITCH + c * 2;
            sm32[SC + o]     = h0v;
            sm32[SC + o + 1] = h1v;
            sm32[SC + CPART + o]     = pk_bf16x2(v.x - fx, v.y - fy);
            sm32[SC + CPART + o + 1] = pk_bf16x2(v.z - fz, v.w - fw);
        }
        __syncthreads();            // C visible; F free to restage

        if (kc + 1 < 4) {           // stage next fp32 chunk (overlaps MMAs)
            #pragma unroll
            for (int k = 0; k < 8; k++) {
                const int idx = k * 256 + tid;
                const int r = idx >> 4, c = idx & 15;
                cpasync16(smemB + (uint32_t)(SF + r * 64 + c * 4) * 4,
                          W1 + (size_t)r * CIN + (kc + 1) * 64 + c * 4);
            }
            asm volatile("cp.async.commit_group;\n");
        }

        const unsigned* bufW = sm32 + SC;
        const unsigned* aH   = sm32 + SAH + kc * 32;
        const unsigned* aL   = sm32 + SAL + kc * 32;

        #pragma unroll
        for (int ks = 0; ks < 4; ks++) {
            const int kp = ks * 8 + q;
            const unsigned aH0 = aH[(ra)      * APITCH + kp];
            const unsigned aH1 = aH[(ra + 8)  * APITCH + kp];
            const unsigned aH2 = aH[(ra)      * APITCH + kp + 4];
            const unsigned aH3 = aH[(ra + 8)  * APITCH + kp + 4];
            const unsigned aH4 = aH[(ra + 16) * APITCH + kp];
            const unsigned aH5 = aH[(ra + 24) * APITCH + kp];
            const unsigned aH6 = aH[(ra + 16) * APITCH + kp + 4];
            const unsigned aH7 = aH[(ra + 24) * APITCH + kp + 4];
            const unsigned aL0 = aL[(ra)      * APITCH + kp];
            const unsigned aL1 = aL[(ra + 8)  * APITCH + kp];
            const unsigned aL2 = aL[(ra)      * APITCH + kp + 4];
            const unsigned aL3 = aL[(ra + 8)  * APITCH + kp + 4];
            const unsigned aL4 = aL[(ra + 16) * APITCH + kp];
            const unsigned aL5 = aL[(ra + 24) * APITCH + kp];
            const unsigned aL6 = aL[(ra + 16) * APITCH + kp + 4];
            const unsigned aL7 = aL[(ra + 24) * APITCH + kp + 4];
            const unsigned bH0 = bufW[h0 * WPITCH + kp];
            const unsigned bH1 = bufW[h0 * WPITCH + kp + 4];
            const unsigned bH2 = bufW[h1 * WPITCH + kp];
            const unsigned bH3 = bufW[h1 * WPITCH + kp + 4];
            const unsigned bL0 = bufW[CPART + h0 * WPITCH + kp];
            const unsigned bL1 = bufW[CPART + h0 * WPITCH + kp + 4];
            const unsigned bL2 = bufW[CPART + h1 * WPITCH + kp];
            const unsigned bL3 = bufW[CPART + h1 * WPITCH + kp + 4];

            // Sh*Wh
            mma16816(acc[0][0], aH0, aH1, aH2, aH3, bH0, bH1);
            mma16816(acc[0][1], aH0, aH1, aH2, aH3, bH2, bH3);
            mma16816(acc[1][0], aH4, aH5, aH6, aH7, bH0, bH1);
            mma16816(acc[1][1], aH4, aH5, aH6, aH7, bH2, bH3);
            // Sh*Wl
            mma16816(acc[0][0], aH0, aH1, aH2, aH3, bL0, bL1);
            mma16816(acc[0][1], aH0, aH1, aH2, aH3, bL2, bL3);
            mma16816(acc[1][0], aH4, aH5, aH6, aH7, bL0, bL1);
            mma16816(acc[1][1], aH4, aH5, aH6, aH7, bL2, bL3);
            // Sl*Wh
            mma16816(acc[0][0], aL0, aL1, aL2, aL3, bH0, bH1);
            mma16816(acc[0][1], aL0, aL1, aL2, aL3, bH2, bH3);
            mma16816(acc[1][0], aL4, aL5, aL6, aL7, bH0, bH1);
            mma16816(acc[1][1], aL4, aL5, aL6, aL7, bH2, bH3);
        }
    }

    // ---- store y into sY (overlays F: dead after last convert) ----
    float* sY = smemf + SYF;
    #pragma unroll
    for (int mt = 0; mt < 2; mt++) {
        #pragma unroll
        for (int nt = 0; nt < 2; nt++) {
            const int col = warp * 16 + nt * 8 + 2 * q;
            const int r0 = mt * 16 + ra;
            if (r0 < NJ)
                *reinterpret_cast<float2*>(sY + r0 * YPAD + col) =
                    make_float2(acc[mt][nt][0], acc[mt][nt][1]);
            if (r0 + 8 < NJ)
                *reinterpret_cast<float2*>(sY + (r0 + 8) * YPAD + col) =
                    make_float2(acc[mt][nt][2], acc[mt][nt][3]);
        }
    }
    __syncthreads();

    // ---- z[n] = sum_h W2[h]*y[n][h] (warp per n) ----
    for (int n = warp; n < NJ; n += 8) {
        const float* yr = sY + n * YPAD;
        float v = sW2[lane]      * yr[lane]
                + sW2[lane + 32] * yr[lane + 32]
                + sW2[lane + 64] * yr[lane + 64]
                + sW2[lane + 96] * yr[lane + 96];
        #pragma unroll
        for (int o = 16; o > 0; o >>= 1)
            v += __shfl_xor_sync(0xffffffffu, v, o);
        if (lane == 0) sZ[n] = v;
    }
    __syncthreads();

    // ---- phase 3 (R13): j on lanes, i = warp + 8t; 8 indep chains/warp ----
    {
        const float alpha = alpha_p[0];
        const float c1 = 0.5f * (1.0f + alpha);
        const float c2 = 0.5f * (1.0f - alpha);
        const ull NEG1  = 0xBF800000BF800000ull;
        const ull AMASK = 0x7FFFFFFF7FFFFFFFull;

        ull accP[4] = {0ull, 0ull, 0ull, 0ull};
        ull accQ[4] = {0ull, 0ull, 0ull, 0ull};
        const int jr = (lane < NJ) ? lane : (NJ - 1);
        const float* yjrow = sY + jr * YPAD;

        #pragma unroll
        for (int hc = 0; hc < 8; hc++) {
            const int hb = hc * 16;
            const ulonglong2 yjA = *reinterpret_cast<const ulonglong2*>(yjrow + hb);
            const ulonglong2 yjB = *reinterpret_cast<const ulonglong2*>(yjrow + hb + 4);
            const ulonglong2 yjC = *reinterpret_cast<const ulonglong2*>(yjrow + hb + 8);
            const ulonglong2 yjD = *reinterpret_cast<const ulonglong2*>(yjrow + hb + 12);
            const ulonglong2 wA  = *reinterpret_cast<const ulonglong2*>(sW2 + hb);
            const ulonglong2 wB  = *reinterpret_cast<const ulonglong2*>(sW2 + hb + 4);
            const ulonglong2 wC  = *reinterpret_cast<const ulonglong2*>(sW2 + hb + 8);
            const ulonglong2 wD  = *reinterpret_cast<const ulonglong2*>(sW2 + hb + 12);

            #pragma unroll
            for (int t = 0; t < 4; t++) {
                const int i = warp + 8 * t;
                if (i < NJ) {
                    const float* yir = sY + i * YPAD + hb;
                    const ulonglong2 yiA = *reinterpret_cast<const ulonglong2*>(yir);
                    const ulonglong2 yiB = *reinterpret_cast<const ulonglong2*>(yir + 4);
                    const ulonglong2 yiC = *reinterpret_cast<const ulonglong2*>(yir + 8);
                    const ulonglong2 yiD = *reinterpret_cast<const ulonglong2*>(yir + 12);
                    ull d;
                    d = yjA.x; fma2(d, yiA.x, NEG1); d &= AMASK; fma2(accP[t], d, wA.x);
                    d = yjA.y; fma2(d, yiA.y, NEG1); d &= AMASK; fma2(accQ[t], d, wA.y);
                    d = yjB.x; fma2(d, yiB.x, NEG1); d &= AMASK; fma2(accP[t], d, wB.x);
                    d = yjB.y; fma2(d, yiB.y, NEG1); d &= AMASK; fma2(accQ[t], d, wB.y);
                    d = yjC.x; fma2(d, yiC.x, NEG1); d &= AMASK; fma2(accP[t], d, wC.x);
                    d = yjC.y; fma2(d, yiC.y, NEG1); d &= AMASK; fma2(accQ[t], d, wC.y);
                    d = yjD.x; fma2(d, yiD.x, NEG1); d &= AMASK; fma2(accP[t], d, wD.x);
                    d = yjD.y; fma2(d, yiD.y, NEG1); d &= AMASK; fma2(accQ[t], d, wD.y);
                }
            }
        }

        float* outB = out + (size_t)b * NJ * NJ;
        if (lane < NJ) {
            const float zj = sZ[lane];
            #pragma unroll
            for (int t = 0; t < 4; t++) {
                const int i = warp + 8 * t;
                if (i < NJ) {
                    const float S = lo2(accP[t]) + hi2(accP[t])
                                  + lo2(accQ[t]) + hi2(accQ[t]);
                    outB[i * NJ + lane] = c1 * (zj - sZ[i]) + c2 * S;
                }
            }
        }
    }
}

extern "C" void kernel_launch(void* const* d_in, const int* in_sizes, int n_in,
                              void* d_out, int out_size)
{
    // metadata order: src, heads, ends, pair_ids, W1, alpha, W2
    const float* src   = (const float*)d_in[0];
    const float* W1    = (const float*)d_in[4];
    const float* alpha = (const float*)d_in[5];
    const float* W2    = (const float*)d_in[6];
    float* out = (float*)d_out;

    cudaFuncSetAttribute(fused_edge_kernel,
                         cudaFuncAttributeMaxDynamicSharedMemorySize, SMEM_BYTES);

    const int batch = in_sizes[0] / (NJ * CIN);          // 256
    fused_edge_kernel<<<batch, 256, SMEM_BYTES>>>(src, W1, alpha, W2, out);
}